// round 9
// baseline (speedup 1.0000x reference)
#include <cuda_runtime.h>

#define NPTS 262144
#define PPL 128
#define DD 64
#define PN ((size_t)PPL * (size_t)NPTS)

typedef unsigned long long u64;

// Scratch (no allocation allowed -> __device__ globals)
__device__ float g_h2[(size_t)NPTS * DD];   // 64 MB: fc2 features (post BN+ReLU)
__device__ float g_scores[NPTS];            // 1 MB : relu(fc3) scores

// ---------------------------------------------------------------------------
// Packed f32x2 helpers (FFMA2 — bit-exact pair of fp32 FMAs)
// ---------------------------------------------------------------------------
__device__ __forceinline__ u64 pack_dup(float x) {
    u64 r;
    asm("mov.b64 %0, {%1, %1};" : "=l"(r) : "f"(x));
    return r;
}
__device__ __forceinline__ u64 pack2(float lo, float hi) {
    u64 r;
    asm("mov.b64 %0, {%1, %2};" : "=l"(r) : "f"(lo), "f"(hi));
    return r;
}
__device__ __forceinline__ void unpack2(u64 v, float& lo, float& hi) {
    asm("mov.b64 {%0, %1}, %2;" : "=f"(lo), "=f"(hi) : "l"(v));
}
__device__ __forceinline__ void ffma2(u64& acc, u64 a, u64 b) {
    asm("fma.rn.f32x2 %0, %1, %2, %0;" : "+l"(acc) : "l"(a), "l"(b));
}

// ---------------------------------------------------------------------------
// Kernel 1: per-point MLP. Block = 128 points x 64 channels, 128 threads.
// Thread tile = 8 points x 8 channels (best LDS-per-FLOP ratio).
// __launch_bounds__(128,4): cap at 128 regs -> 4 blocks/SM = 16 warps (25%).
// Inner loop: per k-quad hoist 16 packed weight u64s (8 LDS.128), then per
// point 1 act LDS.128 + 16 FFMA2 -> live regs ~116, no spills.
// Activations POINT-MAJOR in smem with quad XOR-swizzle q ^ ((pt>>3)&7).
// ---------------------------------------------------------------------------
#define MLP_TPB 128
#define MLP_PTS 128
#define SH_W_FLOATS 4096                   // 64x64 weight tile (16 KB)
#define SH_A_FLOATS (128 * 64)             // point-major activation tile (32 KB)
#define MLP_SMEM_BYTES ((SH_W_FLOATS + SH_A_FLOATS) * 4)

__global__ void __launch_bounds__(MLP_TPB, 4) mlp_kernel(
    const float* __restrict__ feature, const float* __restrict__ feature_geo,
    const float* __restrict__ w1, const float* __restrict__ b1,
    const float* __restrict__ g1, const float* __restrict__ be1,
    const float* __restrict__ m1, const float* __restrict__ v1,
    const float* __restrict__ w2, const float* __restrict__ b2,
    const float* __restrict__ g2, const float* __restrict__ be2,
    const float* __restrict__ m2, const float* __restrict__ v2,
    const float* __restrict__ w3, const float* __restrict__ b3)
{
    extern __shared__ float smem[];
    float* sh_w = smem;                 // SH_W_FLOATS
    float4* sh_a = (float4*)(smem + SH_W_FLOATS);   // [pt*16 + swizzled quad]

    __shared__ float A1[64], C1[64], A2[64], C2[64], W3s[64];
    __shared__ float sh_s[128 * 8];     // per-(point, ch-group) fc3 partials
    __shared__ float B3;

    const int tid = threadIdx.x;
    const int pg  = tid & 15;           // point group: points 8*pg .. 8*pg+7
    const int cg  = tid >> 4;           // chan group : chans  8*cg .. 8*cg+7
    const int swz = pg & 7;             // quad swizzle for this thread's points
    const int base = blockIdx.x * MLP_PTS;

    // Fold BN into per-channel scale/offset: relu(acc*A + C)
    if (tid < 64) {
        float s1 = g1[tid] * rsqrtf(v1[tid] + 1e-5f);
        A1[tid] = s1;
        C1[tid] = (b1[tid] - m1[tid]) * s1 + be1[tid];
        float s2 = g2[tid] * rsqrtf(v2[tid] + 1e-5f);
        A2[tid] = s2;
        C2[tid] = (b2[tid] - m2[tid]) * s2 + be2[tid];
        W3s[tid] = w3[tid];
        if (tid == 0) B3 = b3[0];
    }

    u64 acc[32];                        // acc[p*4+c] = chans (8cg+2c, 8cg+2c+1), point 8pg+p
    #pragma unroll
    for (int i = 0; i < 32; i++) acc[i] = 0ull;

    // ---- Layer 1: K=128 in two halves (half 0 = feature, half 1 = feature_geo)
    for (int kh = 0; kh < 2; kh++) {
        if (kh) __syncthreads();        // previous compute done with buffers
        {   // stage weight half: w1 rows [kh*64, kh*64+64)
            const float4* wsrc = (const float4*)(w1 + kh * 4096);
            float4* wdst = (float4*)sh_w;
            #pragma unroll
            for (int i = tid; i < 1024; i += MLP_TPB) wdst[i] = wsrc[i];
        }
        {   // stage activations point-major, quad-swizzled (conflict-free STS.128)
            const float* src = kh ? feature_geo : feature;
            const float4* fsrc = (const float4*)(src + (size_t)base * 64);
            #pragma unroll
            for (int idx = tid; idx < 2048; idx += MLP_TPB) {
                int pt = idx >> 4;
                int q  = idx & 15;
                sh_a[pt * 16 + (q ^ ((pt >> 3) & 7))] = fsrc[idx];
            }
        }
        __syncthreads();
        #pragma unroll 1
        for (int kq = 0; kq < 16; kq++) {
            // hoist weights for 4 k's x 8 chans: 16 packed u64
            u64 wp[16];
            #pragma unroll
            for (int j = 0; j < 4; j++) {
                const float4* wr = (const float4*)(sh_w + (4 * kq + j) * 64 + 8 * cg);
                float4 wv0 = wr[0], wv1 = wr[1];
                wp[j * 4 + 0] = pack2(wv0.x, wv0.y);
                wp[j * 4 + 1] = pack2(wv0.z, wv0.w);
                wp[j * 4 + 2] = pack2(wv1.x, wv1.y);
                wp[j * 4 + 3] = pack2(wv1.z, wv1.w);
            }
            #pragma unroll
            for (int p = 0; p < 8; p++) {
                float4 a = sh_a[(8 * pg + p) * 16 + (kq ^ swz)];
                u64 ad;
                ad = pack_dup(a.x);
                ffma2(acc[p * 4 + 0], ad, wp[0]);  ffma2(acc[p * 4 + 1], ad, wp[1]);
                ffma2(acc[p * 4 + 2], ad, wp[2]);  ffma2(acc[p * 4 + 3], ad, wp[3]);
                ad = pack_dup(a.y);
                ffma2(acc[p * 4 + 0], ad, wp[4]);  ffma2(acc[p * 4 + 1], ad, wp[5]);
                ffma2(acc[p * 4 + 2], ad, wp[6]);  ffma2(acc[p * 4 + 3], ad, wp[7]);
                ad = pack_dup(a.z);
                ffma2(acc[p * 4 + 0], ad, wp[8]);  ffma2(acc[p * 4 + 1], ad, wp[9]);
                ffma2(acc[p * 4 + 2], ad, wp[10]); ffma2(acc[p * 4 + 3], ad, wp[11]);
                ad = pack_dup(a.w);
                ffma2(acc[p * 4 + 0], ad, wp[12]); ffma2(acc[p * 4 + 1], ad, wp[13]);
                ffma2(acc[p * 4 + 2], ad, wp[14]); ffma2(acc[p * 4 + 3], ad, wp[15]);
            }
        }
    }

    __syncthreads();  // all reads of sh_a (acts) and sh_w (w1) done

    // BN1 + ReLU -> h1 back into sh_a (point-major, same swizzle), as float4s
    #pragma unroll
    for (int p = 0; p < 8; p++) {
        float v[8];
        #pragma unroll
        for (int c = 0; c < 4; c++) unpack2(acc[p * 4 + c], v[2 * c], v[2 * c + 1]);
        float4 lo, hi;
        lo.x = fmaxf(fmaf(v[0], A1[8 * cg + 0], C1[8 * cg + 0]), 0.f);
        lo.y = fmaxf(fmaf(v[1], A1[8 * cg + 1], C1[8 * cg + 1]), 0.f);
        lo.z = fmaxf(fmaf(v[2], A1[8 * cg + 2], C1[8 * cg + 2]), 0.f);
        lo.w = fmaxf(fmaf(v[3], A1[8 * cg + 3], C1[8 * cg + 3]), 0.f);
        hi.x = fmaxf(fmaf(v[4], A1[8 * cg + 4], C1[8 * cg + 4]), 0.f);
        hi.y = fmaxf(fmaf(v[5], A1[8 * cg + 5], C1[8 * cg + 5]), 0.f);
        hi.z = fmaxf(fmaf(v[6], A1[8 * cg + 6], C1[8 * cg + 6]), 0.f);
        hi.w = fmaxf(fmaf(v[7], A1[8 * cg + 7], C1[8 * cg + 7]), 0.f);
        int qb = (8 * pg + p) * 16;
        sh_a[qb + ((2 * cg + 0) ^ swz)] = lo;
        sh_a[qb + ((2 * cg + 1) ^ swz)] = hi;
        acc[p * 4 + 0] = 0ull; acc[p * 4 + 1] = 0ull;
        acc[p * 4 + 2] = 0ull; acc[p * 4 + 3] = 0ull;
    }
    {   // stage w2 (disjoint smem region, concurrent with h1 writes)
        const float4* wsrc = (const float4*)w2;
        float4* wdst = (float4*)sh_w;
        #pragma unroll
        for (int i = tid; i < 1024; i += MLP_TPB) wdst[i] = wsrc[i];
    }
    __syncthreads();

    // ---- Layer 2: K=64
    #pragma unroll 1
    for (int kq = 0; kq < 16; kq++) {
        u64 wp[16];
        #pragma unroll
        for (int j = 0; j < 4; j++) {
            const float4* wr = (const float4*)(sh_w + (4 * kq + j) * 64 + 8 * cg);
            float4 wv0 = wr[0], wv1 = wr[1];
            wp[j * 4 + 0] = pack2(wv0.x, wv0.y);
            wp[j * 4 + 1] = pack2(wv0.z, wv0.w);
            wp[j * 4 + 2] = pack2(wv1.x, wv1.y);
            wp[j * 4 + 3] = pack2(wv1.z, wv1.w);
        }
        #pragma unroll
        for (int p = 0; p < 8; p++) {
            float4 a = sh_a[(8 * pg + p) * 16 + (kq ^ swz)];
            u64 ad;
            ad = pack_dup(a.x);
            ffma2(acc[p * 4 + 0], ad, wp[0]);  ffma2(acc[p * 4 + 1], ad, wp[1]);
            ffma2(acc[p * 4 + 2], ad, wp[2]);  ffma2(acc[p * 4 + 3], ad, wp[3]);
            ad = pack_dup(a.y);
            ffma2(acc[p * 4 + 0], ad, wp[4]);  ffma2(acc[p * 4 + 1], ad, wp[5]);
            ffma2(acc[p * 4 + 2], ad, wp[6]);  ffma2(acc[p * 4 + 3], ad, wp[7]);
            ad = pack_dup(a.z);
            ffma2(acc[p * 4 + 0], ad, wp[8]);  ffma2(acc[p * 4 + 1], ad, wp[9]);
            ffma2(acc[p * 4 + 2], ad, wp[10]); ffma2(acc[p * 4 + 3], ad, wp[11]);
            ad = pack_dup(a.w);
            ffma2(acc[p * 4 + 0], ad, wp[12]); ffma2(acc[p * 4 + 1], ad, wp[13]);
            ffma2(acc[p * 4 + 2], ad, wp[14]); ffma2(acc[p * 4 + 3], ad, wp[15]);
        }
    }

    // BN2 + ReLU -> h2 (direct STG.128), fc3 partials into sh_s
    #pragma unroll
    for (int p = 0; p < 8; p++) {
        float v[8];
        #pragma unroll
        for (int c = 0; c < 4; c++) unpack2(acc[p * 4 + c], v[2 * c], v[2 * c + 1]);
        float s = 0.f;
        #pragma unroll
        for (int j = 0; j < 8; j++) {
            int c = 8 * cg + j;
            v[j] = fmaxf(fmaf(v[j], A2[c], C2[c]), 0.f);
            s = fmaf(v[j], W3s[c], s);
        }
        float* hrow = g_h2 + (size_t)(base + 8 * pg + p) * 64 + 8 * cg;
        ((float4*)hrow)[0] = make_float4(v[0], v[1], v[2], v[3]);
        ((float4*)hrow)[1] = make_float4(v[4], v[5], v[6], v[7]);
        sh_s[(8 * pg + p) * 8 + cg] = s;
    }
    __syncthreads();

    // Final fc3 reduce: thread tid owns point tid
    {
        const float* sp = sh_s + tid * 8;
        float s = B3;
        #pragma unroll
        for (int j = 0; j < 8; j++) s += sp[j];
        g_scores[base + tid] = fmaxf(s, 0.f);
    }
}

// ---------------------------------------------------------------------------
// Kernel 2: zero the pooled-feature region (atomicMax accumulates into it)
// ---------------------------------------------------------------------------
__global__ void zero_feats(float* __restrict__ out) {
    size_t i = (size_t)blockIdx.x * 256 + threadIdx.x;  // 16384 elements
    out[4 * PN + i] = 0.f;
}

// ---------------------------------------------------------------------------
// Kernel 3: per-(plane, point-chunk) masks + compacted masked max-pool.
// grid = (N/2048, P), 256 threads, 4 points/thread x 2 iters, vector I/O.
// Mask outputs use streaming (.cs) stores: written once, keep L2 for h2.
// ---------------------------------------------------------------------------
#define P2_TPB 256
#define P2_PTS 2048
#define P2_ITERS 2

__global__ void __launch_bounds__(P2_TPB) plane_kernel(
    const float* __restrict__ xyz, const float* __restrict__ centers,
    const float* __restrict__ plane_center, const float* __restrict__ plane_normal,
    const float* __restrict__ pmin, const float* __restrict__ pmax,
    float* __restrict__ out)
{
    const int p = blockIdx.y;
    const int base = blockIdx.x * P2_PTS;
    const int tid = threadIdx.x;

    __shared__ unsigned shOn[64], shOff[64];
    __shared__ int lstOn[P2_PTS];
    __shared__ int lstOff[P2_PTS];
    __shared__ int cntOn, cntOff;
    if (tid == 0) { cntOn = 0; cntOff = 0; }
    if (tid < 64) { shOn[tid] = 0u; shOff[tid] = 0u; }

    const float nx = plane_normal[p * 3 + 0];
    const float ny = plane_normal[p * 3 + 1];
    const float nz = plane_normal[p * 3 + 2];
    const float off = plane_center[p * 3 + 0] * nx
                    + plane_center[p * 3 + 1] * ny
                    + plane_center[p * 3 + 2] * nz;
    const float mn0 = pmin[p * 3 + 0], mn1 = pmin[p * 3 + 1], mn2 = pmin[p * 3 + 2];
    const float mx0 = pmax[p * 3 + 0], mx1 = pmax[p * 3 + 1], mx2 = pmax[p * 3 + 2];
    const bool a0 = (mx0 != 0.f), a1 = (mx1 != 0.f), a2 = (mx2 != 0.f);
    const float cx = centers[0], cy = centers[1], cz = centers[2];

    __syncthreads();

    float* oS  = out;
    float* oM  = out + PN;
    float* oOn = out + 2 * PN;
    float* oOf = out + 3 * PN;
    const size_t rowoff = (size_t)p * NPTS;

    #pragma unroll
    for (int i = 0; i < P2_ITERS; i++) {
        const int n = base + (i * P2_TPB + tid) * 4;     // n % 4 == 0
        const float4* xp = (const float4*)(xyz + (size_t)n * 3);
        float4 q0 = xp[0], q1 = xp[1], q2 = xp[2];
        float X[4] = {q0.x, q0.w, q1.z, q2.y};
        float Y[4] = {q0.y, q1.x, q1.w, q2.z};
        float Z[4] = {q0.z, q1.y, q2.x, q2.w};
        float4 sc = *(const float4*)(g_scores + n);
        float S[4] = {sc.x, sc.y, sc.z, sc.w};

        float4 vS, vM, vOn, vOf;
        float* pS  = &vS.x;
        float* pM  = &vM.x;
        float* pOn = &vOn.x;
        float* pOf = &vOf.x;
        #pragma unroll
        for (int u = 0; u < 4; u++) {
            float px = X[u] + cx, py = Y[u] + cy, pz = Z[u] + cz;
            bool rok = (!a0 || (px >= mn0 && px < mx0))
                    && (!a1 || (py >= mn1 && py < mx1))
                    && (!a2 || (pz >= mn2 && pz < mx2));
            float dist = fabsf(px * nx + py * ny + pz * nz - off);
            bool mask = rok && (dist < 0.1f);
            float s = S[u];
            // sigmoid(s) > 0.5  <=>  s > 0   (s >= 0 from relu)
            bool onm  = mask && (s > 0.f);
            bool offm = mask && (s <= 0.f);
            pS[u]  = mask ? s : 0.f;
            pM[u]  = mask ? 1.f : 0.f;
            pOn[u] = onm ? 1.f : 0.f;
            pOf[u] = offm ? 1.f : 0.f;
            if (onm)       lstOn[atomicAdd(&cntOn, 1)] = n + u;
            else if (offm) lstOff[atomicAdd(&cntOff, 1)] = n + u;
        }
        const size_t o = rowoff + n;
        __stcs((float4*)(oS + o),  vS);
        __stcs((float4*)(oM + o),  vM);
        __stcs((float4*)(oOn + o), vOn);
        __stcs((float4*)(oOf + o), vOf);
    }
    __syncthreads();

    // Cooperative masked max-pool of h2 rows: 4 rows in flight x 64 dims.
    const int d = tid & 63;
    const int g = tid >> 6;
    unsigned mOn = 0u, mOf = 0u;
    const int con = cntOn, cof = cntOff;
    for (int idx = g; idx < con; idx += 4) {
        int nn = lstOn[idx];
        mOn = max(mOn, __float_as_uint(g_h2[(size_t)nn * 64 + d]));
    }
    for (int idx = g; idx < cof; idx += 4) {
        int nn = lstOff[idx];
        mOf = max(mOf, __float_as_uint(g_h2[(size_t)nn * 64 + d]));
    }
    if (mOn) atomicMax(&shOn[d], mOn);
    if (mOf) atomicMax(&shOff[d], mOf);
    __syncthreads();

    // h2 >= 0 so uint-bit atomicMax against 0-initialized output is exact.
    if (tid < 64) {
        unsigned v = shOn[tid];
        if (v) atomicMax((unsigned*)(out + 4 * PN + (size_t)p * 64 + tid), v);
    } else if (tid < 128) {
        unsigned v = shOff[tid - 64];
        if (v) atomicMax((unsigned*)(out + 4 * PN + (size_t)PPL * 64 + (size_t)p * 64 + (tid - 64)), v);
    }
}

// ---------------------------------------------------------------------------
extern "C" void kernel_launch(void* const* d_in, const int* in_sizes, int n_in,
                              void* d_out, int out_size) {
    const float* feature      = (const float*)d_in[0];
    const float* feature_geo  = (const float*)d_in[1];
    const float* xyz          = (const float*)d_in[2];
    const float* centers      = (const float*)d_in[3];
    const float* plane_center = (const float*)d_in[4];
    const float* plane_normal = (const float*)d_in[5];
    const float* pxyz_min     = (const float*)d_in[6];
    const float* pxyz_max     = (const float*)d_in[7];
    const float* w1 = (const float*)d_in[8];
    const float* b1 = (const float*)d_in[9];
    const float* g1 = (const float*)d_in[10];
    const float* be1 = (const float*)d_in[11];
    const float* m1 = (const float*)d_in[12];
    const float* v1 = (const float*)d_in[13];
    const float* w2 = (const float*)d_in[14];
    const float* b2 = (const float*)d_in[15];
    const float* g2 = (const float*)d_in[16];
    const float* be2 = (const float*)d_in[17];
    const float* m2 = (const float*)d_in[18];
    const float* v2 = (const float*)d_in[19];
    const float* w3 = (const float*)d_in[20];
    const float* b3 = (const float*)d_in[21];
    float* out = (float*)d_out;

    cudaFuncSetAttribute((const void*)mlp_kernel,
                         cudaFuncAttributeMaxDynamicSharedMemorySize,
                         MLP_SMEM_BYTES);

    mlp_kernel<<<NPTS / MLP_PTS, MLP_TPB, MLP_SMEM_BYTES>>>(
        feature, feature_geo,
        w1, b1, g1, be1, m1, v1,
        w2, b2, g2, be2, m2, v2,
        w3, b3);
    zero_feats<<<64, 256>>>(out);
    dim3 grid2(NPTS / P2_PTS, PPL);
    plane_kernel<<<grid2, P2_TPB>>>(xyz, centers, plane_center, plane_normal,
                                    pxyz_min, pxyz_max, out);
}

// round 10
// speedup vs baseline: 1.6651x; 1.6651x over previous
#include <cuda_runtime.h>
#include <cuda_pipeline.h>

#define NPTS 262144
#define PPL 128
#define DD 64
#define PN ((size_t)PPL * (size_t)NPTS)

typedef unsigned long long u64;

// Scratch (no allocation allowed -> __device__ globals)
__device__ float g_h2[(size_t)NPTS * DD];   // 64 MB: fc2 features (post BN+ReLU)
__device__ float g_scores[NPTS];            // 1 MB : relu(fc3) scores

// ---------------------------------------------------------------------------
// Packed f32x2 helpers (FFMA2 — bit-exact pair of fp32 FMAs)
// ---------------------------------------------------------------------------
__device__ __forceinline__ u64 pack_dup(float x) {
    u64 r;
    asm("mov.b64 %0, {%1, %1};" : "=l"(r) : "f"(x));
    return r;
}
__device__ __forceinline__ u64 pack2(float lo, float hi) {
    u64 r;
    asm("mov.b64 %0, {%1, %2};" : "=l"(r) : "f"(lo), "f"(hi));
    return r;
}
__device__ __forceinline__ void unpack2(u64 v, float& lo, float& hi) {
    asm("mov.b64 {%0, %1}, %2;" : "=f"(lo), "=f"(hi) : "l"(v));
}
__device__ __forceinline__ void ffma2(u64& acc, u64 a, u64 b) {
    asm("fma.rn.f32x2 %0, %1, %2, %0;" : "+l"(acc) : "l"(a), "l"(b));
}

// ---------------------------------------------------------------------------
// Kernel 1: per-point MLP. Block = 128 points x 64 channels, 128 threads.
// Thread tile = 8 points x 8 channels (R7 compute loop, the proven optimum).
// NEW: layer-1 split into four 32-k chunks, cp.async double-buffered:
//   chunk c computes from buffer c&1 while chunk c+2 streams in (LDGSTS).
// Same 48KB smem footprint -> still 3 blocks/SM; staging latency hidden.
// ---------------------------------------------------------------------------
#define MLP_TPB 128
#define MLP_PTS 128
// sh_w: 2 chunk buffers x 2048 floats (8KB each); layer2 uses all 4096 floats
#define SH_W_FLOATS 4096
// sh_a: 2 chunk buffers x 1024 float4 (16KB each); layer2 h1 uses all 2048
#define SH_A_QUADS 2048
#define MLP_SMEM_BYTES (SH_W_FLOATS * 4 + SH_A_QUADS * 16)

__global__ void __launch_bounds__(MLP_TPB) mlp_kernel(
    const float* __restrict__ feature, const float* __restrict__ feature_geo,
    const float* __restrict__ w1, const float* __restrict__ b1,
    const float* __restrict__ g1, const float* __restrict__ be1,
    const float* __restrict__ m1, const float* __restrict__ v1,
    const float* __restrict__ w2, const float* __restrict__ b2,
    const float* __restrict__ g2, const float* __restrict__ be2,
    const float* __restrict__ m2, const float* __restrict__ v2,
    const float* __restrict__ w3, const float* __restrict__ b3)
{
    extern __shared__ float smem[];
    float* sh_w = smem;                             // SH_W_FLOATS
    float4* sh_a = (float4*)(smem + SH_W_FLOATS);   // SH_A_QUADS

    __shared__ float A1[64], C1[64], A2[64], C2[64], W3s[64];
    __shared__ float sh_s[128 * 8];     // per-(point, ch-group) fc3 partials
    __shared__ float B3;

    const int tid = threadIdx.x;
    const int pg  = tid & 15;           // point group: points 8*pg .. 8*pg+7
    const int cg  = tid >> 4;           // chan group : chans  8*cg .. 8*cg+7
    const int swz = pg & 7;             // quad swizzle for this thread's points
    const int base = blockIdx.x * MLP_PTS;

    // --- prologue: prefetch layer-1 chunks 0 and 1 (acts + weights) --------
    // chunk c: source = (c<2 ? feature : geo), k-range [(c&1)*32, (c&1)*32+32)
    //          w1 rows [c*32, c*32+32)
    const float4* fsrc0 = (const float4*)(feature + (size_t)base * 64);
    const float4* fsrc1 = (const float4*)(feature_geo + (size_t)base * 64);
    const float4* w1v = (const float4*)w1;

    #pragma unroll
    for (int c = 0; c < 2; c++) {
        const float4* fs = fsrc0;       // chunks 0,1 are from feature
        float4* abuf = sh_a + (c & 1) * 1024;
        float4* wbuf = (float4*)(sh_w + (c & 1) * 2048);
        int c8 = (c & 1) * 8;
        #pragma unroll
        for (int i = 0; i < 8; i++) {
            int idx = tid + i * 128;
            int pt = idx >> 3, q = idx & 7;
            __pipeline_memcpy_async(&abuf[pt * 8 + (q ^ ((pt >> 3) & 7))],
                                    &fs[pt * 16 + c8 + q], 16);
        }
        #pragma unroll
        for (int i = 0; i < 4; i++) {
            int idx = tid + i * 128;
            __pipeline_memcpy_async(&wbuf[idx], &w1v[c * 512 + idx], 16);
        }
        __pipeline_commit();
    }

    // Fold BN into per-channel scale/offset: relu(acc*A + C)
    if (tid < 64) {
        float s1 = g1[tid] * rsqrtf(v1[tid] + 1e-5f);
        A1[tid] = s1;
        C1[tid] = (b1[tid] - m1[tid]) * s1 + be1[tid];
        float s2 = g2[tid] * rsqrtf(v2[tid] + 1e-5f);
        A2[tid] = s2;
        C2[tid] = (b2[tid] - m2[tid]) * s2 + be2[tid];
        W3s[tid] = w3[tid];
        if (tid == 0) B3 = b3[0];
    }

    u64 acc[32];                        // acc[p*4+c] = chans (8cg+2c, 8cg+2c+1), point 8pg+p
    #pragma unroll
    for (int i = 0; i < 32; i++) acc[i] = 0ull;

    // ---- Layer 1: 4 chunks of 32 k, double-buffered ----
    #pragma unroll 1
    for (int c = 0; c < 4; c++) {
        if (c == 3) __pipeline_wait_prior(0);
        else        __pipeline_wait_prior(1);
        __syncthreads();

        const float* wbuf = sh_w + (c & 1) * 2048;
        const float4* abuf = sh_a + (c & 1) * 1024;

        #pragma unroll 1
        for (int kq = 0; kq < 8; kq++) {
            // hoist weights for 4 k's x 8 chans: 16 packed u64
            u64 wp[16];
            #pragma unroll
            for (int j = 0; j < 4; j++) {
                const float4* wr = (const float4*)(wbuf + (4 * kq + j) * 64 + 8 * cg);
                float4 wv0 = wr[0], wv1 = wr[1];
                wp[j * 4 + 0] = pack2(wv0.x, wv0.y);
                wp[j * 4 + 1] = pack2(wv0.z, wv0.w);
                wp[j * 4 + 2] = pack2(wv1.x, wv1.y);
                wp[j * 4 + 3] = pack2(wv1.z, wv1.w);
            }
            #pragma unroll
            for (int p = 0; p < 8; p++) {
                float4 a = abuf[(8 * pg + p) * 8 + (kq ^ swz)];
                u64 ad;
                ad = pack_dup(a.x);
                ffma2(acc[p * 4 + 0], ad, wp[0]);  ffma2(acc[p * 4 + 1], ad, wp[1]);
                ffma2(acc[p * 4 + 2], ad, wp[2]);  ffma2(acc[p * 4 + 3], ad, wp[3]);
                ad = pack_dup(a.y);
                ffma2(acc[p * 4 + 0], ad, wp[4]);  ffma2(acc[p * 4 + 1], ad, wp[5]);
                ffma2(acc[p * 4 + 2], ad, wp[6]);  ffma2(acc[p * 4 + 3], ad, wp[7]);
                ad = pack_dup(a.z);
                ffma2(acc[p * 4 + 0], ad, wp[8]);  ffma2(acc[p * 4 + 1], ad, wp[9]);
                ffma2(acc[p * 4 + 2], ad, wp[10]); ffma2(acc[p * 4 + 3], ad, wp[11]);
                ad = pack_dup(a.w);
                ffma2(acc[p * 4 + 0], ad, wp[12]); ffma2(acc[p * 4 + 1], ad, wp[13]);
                ffma2(acc[p * 4 + 2], ad, wp[14]); ffma2(acc[p * 4 + 3], ad, wp[15]);
            }
        }
        __syncthreads();                // buffer c&1 free to refill

        if (c < 2) {                    // prefetch chunk c+2 (geo source)
            int cn = c + 2;
            float4* abuf2 = sh_a + (cn & 1) * 1024;
            float4* wbuf2 = (float4*)(sh_w + (cn & 1) * 2048);
            int c8 = (cn & 1) * 8;
            #pragma unroll
            for (int i = 0; i < 8; i++) {
                int idx = tid + i * 128;
                int pt = idx >> 3, q = idx & 7;
                __pipeline_memcpy_async(&abuf2[pt * 8 + (q ^ ((pt >> 3) & 7))],
                                        &fsrc1[pt * 16 + c8 + q], 16);
            }
            #pragma unroll
            for (int i = 0; i < 4; i++) {
                int idx = tid + i * 128;
                __pipeline_memcpy_async(&wbuf2[idx], &w1v[cn * 512 + idx], 16);
            }
            __pipeline_commit();
        }
    }

    // BN1 + ReLU -> h1 into full sh_a (point-major, 16 quads/pt, same swizzle)
    #pragma unroll
    for (int p = 0; p < 8; p++) {
        float v[8];
        #pragma unroll
        for (int c = 0; c < 4; c++) unpack2(acc[p * 4 + c], v[2 * c], v[2 * c + 1]);
        float4 lo, hi;
        lo.x = fmaxf(fmaf(v[0], A1[8 * cg + 0], C1[8 * cg + 0]), 0.f);
        lo.y = fmaxf(fmaf(v[1], A1[8 * cg + 1], C1[8 * cg + 1]), 0.f);
        lo.z = fmaxf(fmaf(v[2], A1[8 * cg + 2], C1[8 * cg + 2]), 0.f);
        lo.w = fmaxf(fmaf(v[3], A1[8 * cg + 3], C1[8 * cg + 3]), 0.f);
        hi.x = fmaxf(fmaf(v[4], A1[8 * cg + 4], C1[8 * cg + 4]), 0.f);
        hi.y = fmaxf(fmaf(v[5], A1[8 * cg + 5], C1[8 * cg + 5]), 0.f);
        hi.z = fmaxf(fmaf(v[6], A1[8 * cg + 6], C1[8 * cg + 6]), 0.f);
        hi.w = fmaxf(fmaf(v[7], A1[8 * cg + 7], C1[8 * cg + 7]), 0.f);
        int qb = (8 * pg + p) * 16;
        sh_a[qb + ((2 * cg + 0) ^ swz)] = lo;
        sh_a[qb + ((2 * cg + 1) ^ swz)] = hi;
        acc[p * 4 + 0] = 0ull; acc[p * 4 + 1] = 0ull;
        acc[p * 4 + 2] = 0ull; acc[p * 4 + 3] = 0ull;
    }
    {   // prefetch w2 into full sh_w (concurrent with h1 writeback)
        const float4* w2v = (const float4*)w2;
        float4* wdst = (float4*)sh_w;
        #pragma unroll
        for (int i = 0; i < 8; i++) {
            int idx = tid + i * 128;
            __pipeline_memcpy_async(&wdst[idx], &w2v[idx], 16);
        }
        __pipeline_commit();
    }
    __pipeline_wait_prior(0);
    __syncthreads();

    // ---- Layer 2: K=64 (acts in full sh_a, 16 quads/pt; weights in sh_w)
    #pragma unroll 1
    for (int kq = 0; kq < 16; kq++) {
        u64 wp[16];
        #pragma unroll
        for (int j = 0; j < 4; j++) {
            const float4* wr = (const float4*)(sh_w + (4 * kq + j) * 64 + 8 * cg);
            float4 wv0 = wr[0], wv1 = wr[1];
            wp[j * 4 + 0] = pack2(wv0.x, wv0.y);
            wp[j * 4 + 1] = pack2(wv0.z, wv0.w);
            wp[j * 4 + 2] = pack2(wv1.x, wv1.y);
            wp[j * 4 + 3] = pack2(wv1.z, wv1.w);
        }
        #pragma unroll
        for (int p = 0; p < 8; p++) {
            float4 a = sh_a[(8 * pg + p) * 16 + (kq ^ swz)];
            u64 ad;
            ad = pack_dup(a.x);
            ffma2(acc[p * 4 + 0], ad, wp[0]);  ffma2(acc[p * 4 + 1], ad, wp[1]);
            ffma2(acc[p * 4 + 2], ad, wp[2]);  ffma2(acc[p * 4 + 3], ad, wp[3]);
            ad = pack_dup(a.y);
            ffma2(acc[p * 4 + 0], ad, wp[4]);  ffma2(acc[p * 4 + 1], ad, wp[5]);
            ffma2(acc[p * 4 + 2], ad, wp[6]);  ffma2(acc[p * 4 + 3], ad, wp[7]);
            ad = pack_dup(a.z);
            ffma2(acc[p * 4 + 0], ad, wp[8]);  ffma2(acc[p * 4 + 1], ad, wp[9]);
            ffma2(acc[p * 4 + 2], ad, wp[10]); ffma2(acc[p * 4 + 3], ad, wp[11]);
            ad = pack_dup(a.w);
            ffma2(acc[p * 4 + 0], ad, wp[12]); ffma2(acc[p * 4 + 1], ad, wp[13]);
            ffma2(acc[p * 4 + 2], ad, wp[14]); ffma2(acc[p * 4 + 3], ad, wp[15]);
        }
    }

    // BN2 + ReLU -> h2 (direct STG.128), fc3 partials into sh_s
    #pragma unroll
    for (int p = 0; p < 8; p++) {
        float v[8];
        #pragma unroll
        for (int c = 0; c < 4; c++) unpack2(acc[p * 4 + c], v[2 * c], v[2 * c + 1]);
        float s = 0.f;
        #pragma unroll
        for (int j = 0; j < 8; j++) {
            int c = 8 * cg + j;
            v[j] = fmaxf(fmaf(v[j], A2[c], C2[c]), 0.f);
            s = fmaf(v[j], W3s[c], s);
        }
        float* hrow = g_h2 + (size_t)(base + 8 * pg + p) * 64 + 8 * cg;
        ((float4*)hrow)[0] = make_float4(v[0], v[1], v[2], v[3]);
        ((float4*)hrow)[1] = make_float4(v[4], v[5], v[6], v[7]);
        sh_s[(8 * pg + p) * 8 + cg] = s;
    }
    __syncthreads();

    // Final fc3 reduce: thread tid owns point tid
    {
        const float* sp = sh_s + tid * 8;
        float s = B3;
        #pragma unroll
        for (int j = 0; j < 8; j++) s += sp[j];
        g_scores[base + tid] = fmaxf(s, 0.f);
    }
}

// ---------------------------------------------------------------------------
// Kernel 2: zero the pooled-feature region (atomicMax accumulates into it)
// ---------------------------------------------------------------------------
__global__ void zero_feats(float* __restrict__ out) {
    size_t i = (size_t)blockIdx.x * 256 + threadIdx.x;  // 16384 elements
    out[4 * PN + i] = 0.f;
}

// ---------------------------------------------------------------------------
// Kernel 3: per-(plane, point-chunk) masks + compacted masked max-pool.
// grid = (N/2048, P), 256 threads, 4 points/thread x 2 iters, vector I/O.
// Mask outputs use streaming (.cs) stores: written once, keep L2 for h2.
// ---------------------------------------------------------------------------
#define P2_TPB 256
#define P2_PTS 2048
#define P2_ITERS 2

__global__ void __launch_bounds__(P2_TPB) plane_kernel(
    const float* __restrict__ xyz, const float* __restrict__ centers,
    const float* __restrict__ plane_center, const float* __restrict__ plane_normal,
    const float* __restrict__ pmin, const float* __restrict__ pmax,
    float* __restrict__ out)
{
    const int p = blockIdx.y;
    const int base = blockIdx.x * P2_PTS;
    const int tid = threadIdx.x;

    __shared__ unsigned shOn[64], shOff[64];
    __shared__ int lstOn[P2_PTS];
    __shared__ int lstOff[P2_PTS];
    __shared__ int cntOn, cntOff;
    if (tid == 0) { cntOn = 0; cntOff = 0; }
    if (tid < 64) { shOn[tid] = 0u; shOff[tid] = 0u; }

    const float nx = plane_normal[p * 3 + 0];
    const float ny = plane_normal[p * 3 + 1];
    const float nz = plane_normal[p * 3 + 2];
    const float off = plane_center[p * 3 + 0] * nx
                    + plane_center[p * 3 + 1] * ny
                    + plane_center[p * 3 + 2] * nz;
    const float mn0 = pmin[p * 3 + 0], mn1 = pmin[p * 3 + 1], mn2 = pmin[p * 3 + 2];
    const float mx0 = pmax[p * 3 + 0], mx1 = pmax[p * 3 + 1], mx2 = pmax[p * 3 + 2];
    const bool a0 = (mx0 != 0.f), a1 = (mx1 != 0.f), a2 = (mx2 != 0.f);
    const float cx = centers[0], cy = centers[1], cz = centers[2];

    __syncthreads();

    float* oS  = out;
    float* oM  = out + PN;
    float* oOn = out + 2 * PN;
    float* oOf = out + 3 * PN;
    const size_t rowoff = (size_t)p * NPTS;

    #pragma unroll
    for (int i = 0; i < P2_ITERS; i++) {
        const int n = base + (i * P2_TPB + tid) * 4;     // n % 4 == 0
        const float4* xp = (const float4*)(xyz + (size_t)n * 3);
        float4 q0 = xp[0], q1 = xp[1], q2 = xp[2];
        float X[4] = {q0.x, q0.w, q1.z, q2.y};
        float Y[4] = {q0.y, q1.x, q1.w, q2.z};
        float Z[4] = {q0.z, q1.y, q2.x, q2.w};
        float4 sc = *(const float4*)(g_scores + n);
        float S[4] = {sc.x, sc.y, sc.z, sc.w};

        float4 vS, vM, vOn, vOf;
        float* pS  = &vS.x;
        float* pM  = &vM.x;
        float* pOn = &vOn.x;
        float* pOf = &vOf.x;
        #pragma unroll
        for (int u = 0; u < 4; u++) {
            float px = X[u] + cx, py = Y[u] + cy, pz = Z[u] + cz;
            bool rok = (!a0 || (px >= mn0 && px < mx0))
                    && (!a1 || (py >= mn1 && py < mx1))
                    && (!a2 || (pz >= mn2 && pz < mx2));
            float dist = fabsf(px * nx + py * ny + pz * nz - off);
            bool mask = rok && (dist < 0.1f);
            float s = S[u];
            // sigmoid(s) > 0.5  <=>  s > 0   (s >= 0 from relu)
            bool onm  = mask && (s > 0.f);
            bool offm = mask && (s <= 0.f);
            pS[u]  = mask ? s : 0.f;
            pM[u]  = mask ? 1.f : 0.f;
            pOn[u] = onm ? 1.f : 0.f;
            pOf[u] = offm ? 1.f : 0.f;
            if (onm)       lstOn[atomicAdd(&cntOn, 1)] = n + u;
            else if (offm) lstOff[atomicAdd(&cntOff, 1)] = n + u;
        }
        const size_t o = rowoff + n;
        __stcs((float4*)(oS + o),  vS);
        __stcs((float4*)(oM + o),  vM);
        __stcs((float4*)(oOn + o), vOn);
        __stcs((float4*)(oOf + o), vOf);
    }
    __syncthreads();

    // Cooperative masked max-pool of h2 rows: 4 rows in flight x 64 dims.
    const int d = tid & 63;
    const int g = tid >> 6;
    unsigned mOn = 0u, mOf = 0u;
    const int con = cntOn, cof = cntOff;
    for (int idx = g; idx < con; idx += 4) {
        int nn = lstOn[idx];
        mOn = max(mOn, __float_as_uint(g_h2[(size_t)nn * 64 + d]));
    }
    for (int idx = g; idx < cof; idx += 4) {
        int nn = lstOff[idx];
        mOf = max(mOf, __float_as_uint(g_h2[(size_t)nn * 64 + d]));
    }
    if (mOn) atomicMax(&shOn[d], mOn);
    if (mOf) atomicMax(&shOff[d], mOf);
    __syncthreads();

    // h2 >= 0 so uint-bit atomicMax against 0-initialized output is exact.
    if (tid < 64) {
        unsigned v = shOn[tid];
        if (v) atomicMax((unsigned*)(out + 4 * PN + (size_t)p * 64 + tid), v);
    } else if (tid < 128) {
        unsigned v = shOff[tid - 64];
        if (v) atomicMax((unsigned*)(out + 4 * PN + (size_t)PPL * 64 + (size_t)p * 64 + (tid - 64)), v);
    }
}

// ---------------------------------------------------------------------------
extern "C" void kernel_launch(void* const* d_in, const int* in_sizes, int n_in,
                              void* d_out, int out_size) {
    const float* feature      = (const float*)d_in[0];
    const float* feature_geo  = (const float*)d_in[1];
    const float* xyz          = (const float*)d_in[2];
    const float* centers      = (const float*)d_in[3];
    const float* plane_center = (const float*)d_in[4];
    const float* plane_normal = (const float*)d_in[5];
    const float* pxyz_min     = (const float*)d_in[6];
    const float* pxyz_max     = (const float*)d_in[7];
    const float* w1 = (const float*)d_in[8];
    const float* b1 = (const float*)d_in[9];
    const float* g1 = (const float*)d_in[10];
    const float* be1 = (const float*)d_in[11];
    const float* m1 = (const float*)d_in[12];
    const float* v1 = (const float*)d_in[13];
    const float* w2 = (const float*)d_in[14];
    const float* b2 = (const float*)d_in[15];
    const float* g2 = (const float*)d_in[16];
    const float* be2 = (const float*)d_in[17];
    const float* m2 = (const float*)d_in[18];
    const float* v2 = (const float*)d_in[19];
    const float* w3 = (const float*)d_in[20];
    const float* b3 = (const float*)d_in[21];
    float* out = (float*)d_out;

    cudaFuncSetAttribute((const void*)mlp_kernel,
                         cudaFuncAttributeMaxDynamicSharedMemorySize,
                         MLP_SMEM_BYTES);

    mlp_kernel<<<NPTS / MLP_PTS, MLP_TPB, MLP_SMEM_BYTES>>>(
        feature, feature_geo,
        w1, b1, g1, be1, m1, v1,
        w2, b2, g2, be2, m2, v2,
        w3, b3);
    zero_feats<<<64, 256>>>(out);
    dim3 grid2(NPTS / P2_PTS, PPL);
    plane_kernel<<<grid2, P2_TPB>>>(xyz, centers, plane_center, plane_normal,
                                    pxyz_min, pxyz_max, out);
}

// round 12
// speedup vs baseline: 1.6810x; 1.0096x over previous
#include <cuda_runtime.h>
#include <cuda_pipeline.h>
#include <cstdint>

#define NPTS 262144
#define PPL 128
#define DD 64
#define PN ((size_t)PPL * (size_t)NPTS)

typedef unsigned long long u64;

// Scratch (no allocation allowed -> __device__ globals)
__device__ float g_h2[(size_t)NPTS * DD];        // 64 MB: fc2 features (post BN+ReLU)
__device__ unsigned g_onbits[PPL * (NPTS / 32)]; // 4 MB: per-(plane,warp) on-mask bits
__device__ unsigned g_offbits[PPL * (NPTS / 32)];// 4 MB: off-mask bits

// ---------------------------------------------------------------------------
// Packed f32x2 helpers (FFMA2 — bit-exact pair of fp32 FMAs)
// ---------------------------------------------------------------------------
__device__ __forceinline__ u64 pack_dup(float x) {
    u64 r;
    asm("mov.b64 %0, {%1, %1};" : "=l"(r) : "f"(x));
    return r;
}
__device__ __forceinline__ u64 pack2(float lo, float hi) {
    u64 r;
    asm("mov.b64 %0, {%1, %2};" : "=l"(r) : "f"(lo), "f"(hi));
    return r;
}
__device__ __forceinline__ void unpack2(u64 v, float& lo, float& hi) {
    asm("mov.b64 {%0, %1}, %2;" : "=f"(lo), "=f"(hi) : "l"(v));
}
__device__ __forceinline__ void ffma2(u64& acc, u64 a, u64 b) {
    asm("fma.rn.f32x2 %0, %1, %2, %0;" : "+l"(acc) : "l"(a), "l"(b));
}

// ---------------------------------------------------------------------------
// Kernel 1: per-point MLP (R10 pipeline) + FUSED per-plane mask phase.
// Block = 128 points x 64 channels, 128 threads, cp.async double-buffered L1.
// After the MLP epilogue, the block loops all 128 planes: computes masks for
// its 128 points, writes the 4 P x N output arrays (.cs streaming stores),
// and emits on/off bitmasks for the pool kernel.
// ---------------------------------------------------------------------------
#define MLP_TPB 128
#define MLP_PTS 128
#define SH_W_FLOATS 4096
#define SH_A_QUADS 2048
#define MLP_SMEM_BYTES (SH_W_FLOATS * 4 + SH_A_QUADS * 16)

__global__ void __launch_bounds__(MLP_TPB) mlp_kernel(
    const float* __restrict__ feature, const float* __restrict__ feature_geo,
    const float* __restrict__ w1, const float* __restrict__ b1,
    const float* __restrict__ g1, const float* __restrict__ be1,
    const float* __restrict__ m1, const float* __restrict__ v1,
    const float* __restrict__ w2, const float* __restrict__ b2,
    const float* __restrict__ g2, const float* __restrict__ be2,
    const float* __restrict__ m2, const float* __restrict__ v2,
    const float* __restrict__ w3, const float* __restrict__ b3,
    const float* __restrict__ xyz, const float* __restrict__ centers,
    const float* __restrict__ plane_center, const float* __restrict__ plane_normal,
    const float* __restrict__ pmin, const float* __restrict__ pmax,
    float* __restrict__ out)
{
    extern __shared__ float smemf[];
    float* sh_w = smemf;                             // SH_W_FLOATS
    float4* sh_a = (float4*)(smemf + SH_W_FLOATS);   // SH_A_QUADS

    __shared__ float A1[64], C1[64], A2[64], C2[64], W3s[64];
    __shared__ float sh_s[128 * 8];
    __shared__ float B3;

    const int tid = threadIdx.x;
    const int pg  = tid & 15;
    const int cg  = tid >> 4;
    const int swz = pg & 7;
    const int base = blockIdx.x * MLP_PTS;

    // --- prologue: prefetch layer-1 chunks 0 and 1 (acts + weights) --------
    const float4* fsrc0 = (const float4*)(feature + (size_t)base * 64);
    const float4* fsrc1 = (const float4*)(feature_geo + (size_t)base * 64);
    const float4* w1v = (const float4*)w1;

    #pragma unroll
    for (int c = 0; c < 2; c++) {
        const float4* fs = fsrc0;
        float4* abuf = sh_a + (c & 1) * 1024;
        float4* wbuf = (float4*)(sh_w + (c & 1) * 2048);
        int c8 = (c & 1) * 8;
        #pragma unroll
        for (int i = 0; i < 8; i++) {
            int idx = tid + i * 128;
            int pt = idx >> 3, q = idx & 7;
            __pipeline_memcpy_async(&abuf[pt * 8 + (q ^ ((pt >> 3) & 7))],
                                    &fs[pt * 16 + c8 + q], 16);
        }
        #pragma unroll
        for (int i = 0; i < 4; i++) {
            int idx = tid + i * 128;
            __pipeline_memcpy_async(&wbuf[idx], &w1v[c * 512 + idx], 16);
        }
        __pipeline_commit();
    }

    if (tid < 64) {
        float s1 = g1[tid] * rsqrtf(v1[tid] + 1e-5f);
        A1[tid] = s1;
        C1[tid] = (b1[tid] - m1[tid]) * s1 + be1[tid];
        float s2 = g2[tid] * rsqrtf(v2[tid] + 1e-5f);
        A2[tid] = s2;
        C2[tid] = (b2[tid] - m2[tid]) * s2 + be2[tid];
        W3s[tid] = w3[tid];
        if (tid == 0) B3 = b3[0];
    }

    u64 acc[32];
    #pragma unroll
    for (int i = 0; i < 32; i++) acc[i] = 0ull;

    // ---- Layer 1: 4 chunks of 32 k, double-buffered ----
    #pragma unroll 1
    for (int c = 0; c < 4; c++) {
        if (c == 3) __pipeline_wait_prior(0);
        else        __pipeline_wait_prior(1);
        __syncthreads();

        const float* wbuf = sh_w + (c & 1) * 2048;
        const float4* abuf = sh_a + (c & 1) * 1024;

        #pragma unroll 1
        for (int kq = 0; kq < 8; kq++) {
            u64 wp[16];
            #pragma unroll
            for (int j = 0; j < 4; j++) {
                const float4* wr = (const float4*)(wbuf + (4 * kq + j) * 64 + 8 * cg);
                float4 wv0 = wr[0], wv1 = wr[1];
                wp[j * 4 + 0] = pack2(wv0.x, wv0.y);
                wp[j * 4 + 1] = pack2(wv0.z, wv0.w);
                wp[j * 4 + 2] = pack2(wv1.x, wv1.y);
                wp[j * 4 + 3] = pack2(wv1.z, wv1.w);
            }
            #pragma unroll
            for (int p = 0; p < 8; p++) {
                float4 a = abuf[(8 * pg + p) * 8 + (kq ^ swz)];
                u64 ad;
                ad = pack_dup(a.x);
                ffma2(acc[p * 4 + 0], ad, wp[0]);  ffma2(acc[p * 4 + 1], ad, wp[1]);
                ffma2(acc[p * 4 + 2], ad, wp[2]);  ffma2(acc[p * 4 + 3], ad, wp[3]);
                ad = pack_dup(a.y);
                ffma2(acc[p * 4 + 0], ad, wp[4]);  ffma2(acc[p * 4 + 1], ad, wp[5]);
                ffma2(acc[p * 4 + 2], ad, wp[6]);  ffma2(acc[p * 4 + 3], ad, wp[7]);
                ad = pack_dup(a.z);
                ffma2(acc[p * 4 + 0], ad, wp[8]);  ffma2(acc[p * 4 + 1], ad, wp[9]);
                ffma2(acc[p * 4 + 2], ad, wp[10]); ffma2(acc[p * 4 + 3], ad, wp[11]);
                ad = pack_dup(a.w);
                ffma2(acc[p * 4 + 0], ad, wp[12]); ffma2(acc[p * 4 + 1], ad, wp[13]);
                ffma2(acc[p * 4 + 2], ad, wp[14]); ffma2(acc[p * 4 + 3], ad, wp[15]);
            }
        }
        __syncthreads();

        if (c < 2) {
            int cn = c + 2;
            float4* abuf2 = sh_a + (cn & 1) * 1024;
            float4* wbuf2 = (float4*)(sh_w + (cn & 1) * 2048);
            int c8 = (cn & 1) * 8;
            #pragma unroll
            for (int i = 0; i < 8; i++) {
                int idx = tid + i * 128;
                int pt = idx >> 3, q = idx & 7;
                __pipeline_memcpy_async(&abuf2[pt * 8 + (q ^ ((pt >> 3) & 7))],
                                        &fsrc1[pt * 16 + c8 + q], 16);
            }
            #pragma unroll
            for (int i = 0; i < 4; i++) {
                int idx = tid + i * 128;
                __pipeline_memcpy_async(&wbuf2[idx], &w1v[cn * 512 + idx], 16);
            }
            __pipeline_commit();
        }
    }

    // BN1 + ReLU -> h1 into full sh_a
    #pragma unroll
    for (int p = 0; p < 8; p++) {
        float v[8];
        #pragma unroll
        for (int c = 0; c < 4; c++) unpack2(acc[p * 4 + c], v[2 * c], v[2 * c + 1]);
        float4 lo, hi;
        lo.x = fmaxf(fmaf(v[0], A1[8 * cg + 0], C1[8 * cg + 0]), 0.f);
        lo.y = fmaxf(fmaf(v[1], A1[8 * cg + 1], C1[8 * cg + 1]), 0.f);
        lo.z = fmaxf(fmaf(v[2], A1[8 * cg + 2], C1[8 * cg + 2]), 0.f);
        lo.w = fmaxf(fmaf(v[3], A1[8 * cg + 3], C1[8 * cg + 3]), 0.f);
        hi.x = fmaxf(fmaf(v[4], A1[8 * cg + 4], C1[8 * cg + 4]), 0.f);
        hi.y = fmaxf(fmaf(v[5], A1[8 * cg + 5], C1[8 * cg + 5]), 0.f);
        hi.z = fmaxf(fmaf(v[6], A1[8 * cg + 6], C1[8 * cg + 6]), 0.f);
        hi.w = fmaxf(fmaf(v[7], A1[8 * cg + 7], C1[8 * cg + 7]), 0.f);
        int qb = (8 * pg + p) * 16;
        sh_a[qb + ((2 * cg + 0) ^ swz)] = lo;
        sh_a[qb + ((2 * cg + 1) ^ swz)] = hi;
        acc[p * 4 + 0] = 0ull; acc[p * 4 + 1] = 0ull;
        acc[p * 4 + 2] = 0ull; acc[p * 4 + 3] = 0ull;
    }
    {   // prefetch w2
        const float4* w2v = (const float4*)w2;
        float4* wdst = (float4*)sh_w;
        #pragma unroll
        for (int i = 0; i < 8; i++) {
            int idx = tid + i * 128;
            __pipeline_memcpy_async(&wdst[idx], &w2v[idx], 16);
        }
        __pipeline_commit();
    }
    __pipeline_wait_prior(0);
    __syncthreads();

    // ---- Layer 2: K=64
    #pragma unroll 1
    for (int kq = 0; kq < 16; kq++) {
        u64 wp[16];
        #pragma unroll
        for (int j = 0; j < 4; j++) {
            const float4* wr = (const float4*)(sh_w + (4 * kq + j) * 64 + 8 * cg);
            float4 wv0 = wr[0], wv1 = wr[1];
            wp[j * 4 + 0] = pack2(wv0.x, wv0.y);
            wp[j * 4 + 1] = pack2(wv0.z, wv0.w);
            wp[j * 4 + 2] = pack2(wv1.x, wv1.y);
            wp[j * 4 + 3] = pack2(wv1.z, wv1.w);
        }
        #pragma unroll
        for (int p = 0; p < 8; p++) {
            float4 a = sh_a[(8 * pg + p) * 16 + (kq ^ swz)];
            u64 ad;
            ad = pack_dup(a.x);
            ffma2(acc[p * 4 + 0], ad, wp[0]);  ffma2(acc[p * 4 + 1], ad, wp[1]);
            ffma2(acc[p * 4 + 2], ad, wp[2]);  ffma2(acc[p * 4 + 3], ad, wp[3]);
            ad = pack_dup(a.y);
            ffma2(acc[p * 4 + 0], ad, wp[4]);  ffma2(acc[p * 4 + 1], ad, wp[5]);
            ffma2(acc[p * 4 + 2], ad, wp[6]);  ffma2(acc[p * 4 + 3], ad, wp[7]);
            ad = pack_dup(a.z);
            ffma2(acc[p * 4 + 0], ad, wp[8]);  ffma2(acc[p * 4 + 1], ad, wp[9]);
            ffma2(acc[p * 4 + 2], ad, wp[10]); ffma2(acc[p * 4 + 3], ad, wp[11]);
            ad = pack_dup(a.w);
            ffma2(acc[p * 4 + 0], ad, wp[12]); ffma2(acc[p * 4 + 1], ad, wp[13]);
            ffma2(acc[p * 4 + 2], ad, wp[14]); ffma2(acc[p * 4 + 3], ad, wp[15]);
        }
    }

    // BN2 + ReLU -> h2 (direct STG.128), fc3 partials into sh_s
    #pragma unroll
    for (int p = 0; p < 8; p++) {
        float v[8];
        #pragma unroll
        for (int c = 0; c < 4; c++) unpack2(acc[p * 4 + c], v[2 * c], v[2 * c + 1]);
        float s = 0.f;
        #pragma unroll
        for (int j = 0; j < 8; j++) {
            int c = 8 * cg + j;
            v[j] = fmaxf(fmaf(v[j], A2[c], C2[c]), 0.f);
            s = fmaf(v[j], W3s[c], s);
        }
        float* hrow = g_h2 + (size_t)(base + 8 * pg + p) * 64 + 8 * cg;
        ((float4*)hrow)[0] = make_float4(v[0], v[1], v[2], v[3]);
        ((float4*)hrow)[1] = make_float4(v[4], v[5], v[6], v[7]);
        sh_s[(8 * pg + p) * 8 + cg] = s;
    }
    __syncthreads();   // sh_s complete; sh_w/sh_a dead -> reusable for planes

    // ---- stage plane params into (dead) dynamic smem: [p*10 + j]
    float* PP = smemf;
    if (tid < 128) {
        int p = tid;
        float nx = plane_normal[p * 3 + 0];
        float ny = plane_normal[p * 3 + 1];
        float nz = plane_normal[p * 3 + 2];
        PP[p * 10 + 0] = nx;
        PP[p * 10 + 1] = ny;
        PP[p * 10 + 2] = nz;
        PP[p * 10 + 3] = plane_center[p * 3 + 0] * nx
                       + plane_center[p * 3 + 1] * ny
                       + plane_center[p * 3 + 2] * nz;
        PP[p * 10 + 4] = pmin[p * 3 + 0];
        PP[p * 10 + 5] = pmin[p * 3 + 1];
        PP[p * 10 + 6] = pmin[p * 3 + 2];
        PP[p * 10 + 7] = pmax[p * 3 + 0];
        PP[p * 10 + 8] = pmax[p * 3 + 1];
        PP[p * 10 + 9] = pmax[p * 3 + 2];
    }

    // fc3 reduce: thread tid owns point n = base + tid
    float s;
    {
        const float* sp = sh_s + tid * 8;
        s = B3;
        #pragma unroll
        for (int j = 0; j < 8; j++) s += sp[j];
        s = fmaxf(s, 0.f);
    }
    __syncthreads();

    // ---- fused mask phase: this thread's point vs all 128 planes
    {
        const int n = base + tid;
        const float px = xyz[n * 3 + 0] + centers[0];
        const float py = xyz[n * 3 + 1] + centers[1];
        const float pz = xyz[n * 3 + 2] + centers[2];
        const int lane = tid & 31;
        const int word = n >> 5;
        float* oS  = out;
        float* oM  = out + PN;
        float* oOn = out + 2 * PN;
        float* oOf = out + 3 * PN;

        #pragma unroll 4
        for (int p = 0; p < 128; p++) {
            const float* pp = PP + p * 10;
            float nx = pp[0], ny = pp[1], nz = pp[2], off = pp[3];
            float mn0 = pp[4], mn1 = pp[5], mn2 = pp[6];
            float mx0 = pp[7], mx1 = pp[8], mx2 = pp[9];
            bool rok = (mx0 == 0.f || (px >= mn0 && px < mx0))
                    && (mx1 == 0.f || (py >= mn1 && py < mx1))
                    && (mx2 == 0.f || (pz >= mn2 && pz < mx2));
            float dist = fabsf(px * nx + py * ny + pz * nz - off);
            bool mask = rok && (dist < 0.1f);
            // sigmoid(s) > 0.5  <=>  s > 0   (s >= 0 from relu)
            bool onm  = mask && (s > 0.f);
            bool offm = mask && (s <= 0.f);
            size_t o = (size_t)p * NPTS + n;
            __stcs(oS + o,  mask ? s : 0.f);
            __stcs(oM + o,  mask ? 1.f : 0.f);
            __stcs(oOn + o, onm ? 1.f : 0.f);
            __stcs(oOf + o, offm ? 1.f : 0.f);
            unsigned bOn  = __ballot_sync(0xffffffffu, onm);
            unsigned bOff = __ballot_sync(0xffffffffu, offm);
            if (lane == 0) {
                g_onbits[p * (NPTS / 32) + word]  = bOn;
                g_offbits[p * (NPTS / 32) + word] = bOff;
            }
        }
    }
}

// ---------------------------------------------------------------------------
// Kernel 2: zero the pooled-feature region (atomicMax accumulates into it)
// ---------------------------------------------------------------------------
__global__ void zero_feats(float* __restrict__ out) {
    size_t i = (size_t)blockIdx.x * 256 + threadIdx.x;  // 16384 elements
    out[4 * PN + i] = 0.f;
}

// ---------------------------------------------------------------------------
// Kernel 3: pool-only. Expand bitmask -> lists, gather h2, atomicMax.
// grid = (N/2048, P), 256 threads.
// ---------------------------------------------------------------------------
#define P2_TPB 256
#define P2_PTS 2048

__global__ void __launch_bounds__(P2_TPB) pool_kernel(float* __restrict__ out)
{
    const int p = blockIdx.y;
    const int cbase = blockIdx.x * P2_PTS;
    const int tid = threadIdx.x;

    __shared__ unsigned shOn[64], shOff[64];
    __shared__ int lstOn[P2_PTS];
    __shared__ int lstOff[P2_PTS];
    __shared__ int cntOn, cntOff;
    if (tid == 0) { cntOn = 0; cntOff = 0; }
    if (tid < 64) { shOn[tid] = 0u; shOff[tid] = 0u; }
    __syncthreads();

    // expand bitmasks (64 words each) into compact point lists
    if (tid < 64) {
        unsigned w = g_onbits[p * (NPTS / 32) + (cbase >> 5) + tid];
        int bn = cbase + tid * 32;
        while (w) {
            int b = __ffs(w) - 1;
            w &= w - 1;
            lstOn[atomicAdd(&cntOn, 1)] = bn + b;
        }
    } else if (tid < 128) {
        int t = tid - 64;
        unsigned w = g_offbits[p * (NPTS / 32) + (cbase >> 5) + t];
        int bn = cbase + t * 32;
        while (w) {
            int b = __ffs(w) - 1;
            w &= w - 1;
            lstOff[atomicAdd(&cntOff, 1)] = bn + b;
        }
    }
    __syncthreads();

    // Cooperative masked max-pool of h2 rows: 4 rows in flight x 64 dims.
    const int d = tid & 63;
    const int g = tid >> 6;
    unsigned mOn = 0u, mOf = 0u;
    const int con = cntOn, cof = cntOff;
    for (int idx = g; idx < con; idx += 4) {
        int nn = lstOn[idx];
        mOn = max(mOn, __float_as_uint(g_h2[(size_t)nn * 64 + d]));
    }
    for (int idx = g; idx < cof; idx += 4) {
        int nn = lstOff[idx];
        mOf = max(mOf, __float_as_uint(g_h2[(size_t)nn * 64 + d]));
    }
    if (mOn) atomicMax(&shOn[d], mOn);
    if (mOf) atomicMax(&shOff[d], mOf);
    __syncthreads();

    // h2 >= 0 so uint-bit atomicMax against 0-initialized output is exact.
    if (tid < 64) {
        unsigned v = shOn[tid];
        if (v) atomicMax((unsigned*)(out + 4 * PN + (size_t)p * 64 + tid), v);
    } else if (tid < 128) {
        unsigned v = shOff[tid - 64];
        if (v) atomicMax((unsigned*)(out + 4 * PN + (size_t)PPL * 64 + (size_t)p * 64 + (tid - 64)), v);
    }
}

// ---------------------------------------------------------------------------
extern "C" void kernel_launch(void* const* d_in, const int* in_sizes, int n_in,
                              void* d_out, int out_size) {
    const float* feature      = (const float*)d_in[0];
    const float* feature_geo  = (const float*)d_in[1];
    const float* xyz          = (const float*)d_in[2];
    const float* centers      = (const float*)d_in[3];
    const float* plane_center = (const float*)d_in[4];
    const float* plane_normal = (const float*)d_in[5];
    const float* pxyz_min     = (const float*)d_in[6];
    const float* pxyz_max     = (const float*)d_in[7];
    const float* w1 = (const float*)d_in[8];
    const float* b1 = (const float*)d_in[9];
    const float* g1 = (const float*)d_in[10];
    const float* be1 = (const float*)d_in[11];
    const float* m1 = (const float*)d_in[12];
    const float* v1 = (const float*)d_in[13];
    const float* w2 = (const float*)d_in[14];
    const float* b2 = (const float*)d_in[15];
    const float* g2 = (const float*)d_in[16];
    const float* be2 = (const float*)d_in[17];
    const float* m2 = (const float*)d_in[18];
    const float* v2 = (const float*)d_in[19];
    const float* w3 = (const float*)d_in[20];
    const float* b3 = (const float*)d_in[21];
    float* out = (float*)d_out;

    cudaFuncSetAttribute((const void*)mlp_kernel,
                         cudaFuncAttributeMaxDynamicSharedMemorySize,
                         MLP_SMEM_BYTES);

    zero_feats<<<64, 256>>>(out);
    mlp_kernel<<<NPTS / MLP_PTS, MLP_TPB, MLP_SMEM_BYTES>>>(
        feature, feature_geo,
        w1, b1, g1, be1, m1, v1,
        w2, b2, g2, be2, m2, v2,
        w3, b3,
        xyz, centers, plane_center, plane_normal,
        pxyz_min, pxyz_max, out);
    dim3 grid2(NPTS / P2_PTS, PPL);
    pool_kernel<<<grid2, P2_TPB>>>(out);
}